// round 2
// baseline (speedup 1.0000x reference)
#include <cuda_runtime.h>
#include <math.h>

#define BT   64     // threads per block = frames per block
#define FPF  153    // floats per frame (51 joints * 3)
#define NF   114    // output features
#define HW   9      // halo floats per frame (joints 0,21,42)

#define SM_FR   (BT * FPF)          // 9792 floats
#define SM_HALO ((BT + 4) * HW)     // 612 floats
#define SM_OUT  (BT * NF)           // 7296 floats
#define SMEM_BYTES ((SM_FR + SM_HALO + SM_OUT) * 4)   // 70800 bytes

__device__ __forceinline__ float3 f3sub(float3 a, float3 b){ return make_float3(a.x-b.x, a.y-b.y, a.z-b.z); }
__device__ __forceinline__ float  f3dot(float3 a, float3 b){ return a.x*b.x + a.y*b.y + a.z*b.z; }
__device__ __forceinline__ float3 f3cross(float3 a, float3 b){
    return make_float3(a.y*b.z - a.z*b.y, a.z*b.x - a.x*b.z, a.x*b.y - a.y*b.x);
}
__device__ __forceinline__ float  f3n(float3 a){ return sqrtf(f3dot(a,a)); }
__device__ __forceinline__ float  fdist(float3 a, float3 b){
    float3 d = f3sub(a,b); return sqrtf(f3dot(d,d) + 1e-6f);
}
__device__ __forceinline__ float ac(float c){
    c = fminf(fmaxf(c, -1.0f + 1e-6f), 1.0f - 1e-6f);
    return acosf(c);
}
__device__ __forceinline__ void cidx(int t, int T, int& lo, int& hi){
    if (t == 0)        { lo = 0;     hi = 2;     }
    else if (t == T-1) { lo = T - 3; hi = T - 1; }
    else               { lo = t - 1; hi = t + 1; }
}

extern __shared__ float smem_dyn[];

__global__ void __launch_bounds__(BT)
geo_kernel(const float* __restrict__ xyz,
           const float* __restrict__ fmask,
           const float* __restrict__ bmask,
           float* __restrict__ out, int T)
{
    float* sm   = smem_dyn;                 // [BT*FPF]   full frames
    float* halo = sm + SM_FR;               // [(BT+4)*HW] joints 0,21,42 halo
    float* so   = halo + SM_HALO;           // [BT*NF]    output staging

    const int tid = threadIdx.x;
    const long long g0 = (long long)blockIdx.x * BT;
    const int b  = (int)(g0 / T);
    const int t0 = (int)(g0 % T);

    // ---- coalesced main load (block-aligned, 16B-aligned) ----
    {
        const float4* src4 = (const float4*)(xyz + ((long long)b * T + t0) * FPF);
        float4* sm4 = (float4*)sm;
        const int n4 = BT * FPF / 4;          // 2448
        for (int i = tid; i < n4; i += BT) sm4[i] = src4[i];
    }
    // ---- halo load: joints 0,21,42, frames t0-2 .. t0+BT+1 ----
    {
        const float* fb = xyz + (long long)b * T * FPF;
        for (int i = tid; i < SM_HALO; i += BT){
            int f = i / HW, jc = i % HW;
            int s = t0 - 2 + f;
            float v = 0.0f;
            if (s >= 0 && s < T){
                int j = (jc < 3) ? 0 : ((jc < 6) ? 21 : 42);
                v = fb[(long long)s * FPF + j * 3 + (jc % 3)];
            }
            halo[i] = v;
        }
    }
    __syncthreads();

    const int t   = t0 + tid;
    const int smb = tid * FPF;
    #define PJ(j) make_float3(sm[smb + (j)*3], sm[smb + (j)*3 + 1], sm[smb + (j)*3 + 2])
    #define HLD(f, w) make_float3(halo[(f)*HW + (w)*3], halo[(f)*HW + (w)*3 + 1], halo[(f)*HW + (w)*3 + 2])
    const int hb = t0 - 2;   // halo frame index = s - hb

    float* o = so + tid * NF;               // staged output for this frame
    const float fg = fmask[(long long)b * T + t];
    const float bg = bmask[(long long)b * T + t];

    // ---- per-hand: tips(5), curls(5), cross, d_ti ----
    #pragma unroll
    for (int h = 0; h < 2; ++h){
        const int bs = h * 21;
        float* oo = o + h * 12;
        float3 tT = PJ(bs+4),  iT = PJ(bs+8),  mT = PJ(bs+12), rT = PJ(bs+16), pT = PJ(bs+20);
        oo[0] = fdist(tT,iT); oo[1] = fdist(iT,mT); oo[2] = fdist(mT,rT);
        oo[3] = fdist(rT,pT); oo[4] = fdist(tT,pT);
        float3 tM = PJ(bs+2),  iM = PJ(bs+5),  mM = PJ(bs+9),  rM = PJ(bs+13), pM = PJ(bs+17);
        float3 tI = PJ(bs+3),  iP = PJ(bs+6),  mP = PJ(bs+10), rP = PJ(bs+14), pP = PJ(bs+18);
        oo[5] = fdist(tM,tT) / (fdist(tM,tI) + 1e-4f);
        oo[6] = fdist(iM,iT) / (fdist(iM,iP) + 1e-4f);
        oo[7] = fdist(mM,mT) / (fdist(mM,mP) + 1e-4f);
        oo[8] = fdist(rM,rT) / (fdist(rM,rP) + 1e-4f);
        oo[9] = fdist(pM,pT) / (fdist(pM,pP) + 1e-4f);
        oo[10] = iT.x - mT.x;
        oo[11] = fdist(tT, iM);
    }

    // ---- face (x fg) ----
    float3 w0 = PJ(0), w1 = PJ(21), nose = PJ(42), chin = PJ(43), fh = PJ(44);
    float3 iT0 = PJ(8), iT1 = PJ(29);
    o[24] = fdist(w0,nose)*fg;  o[25] = fdist(w0,chin)*fg;  o[26] = fdist(w0,fh)*fg;
    o[27] = fdist(w1,nose)*fg;  o[28] = fdist(w1,chin)*fg;  o[29] = fdist(w1,fh)*fg;
    o[30] = fdist(iT0,nose)*fg; o[31] = fdist(iT0,fh)*fg;
    o[32] = fdist(iT1,nose)*fg; o[33] = fdist(iT1,fh)*fg;

    // ---- 30 joint angles ----
    {
        const int TPp[15] = {0,1,2, 0,5,6, 0,9,10, 0,13,14, 0,17,18};
        const int TJj[15] = {1,2,3, 5,6,7, 9,10,11, 13,14,15, 17,18,19};
        const int TCc[15] = {2,3,4, 6,7,8, 10,11,12, 14,15,16, 18,19,20};
        #pragma unroll
        for (int h = 0; h < 2; ++h){
            const int bs = h * 21;
            #pragma unroll
            for (int k = 0; k < 15; ++k){
                float3 pj = PJ(bs + TJj[k]);
                float3 v1 = f3sub(PJ(bs + TPp[k]), pj);
                float3 v2 = f3sub(PJ(bs + TCc[k]), pj);
                o[34 + h*15 + k] = ac(f3dot(v1,v2) / (f3n(v1)*f3n(v2) + 1e-6f));
            }
        }
    }

    // ---- palm normals ----
    float3 nh[2];
    #pragma unroll
    for (int h = 0; h < 2; ++h){
        const int bs = h * 21;
        float3 w = h ? w1 : w0;
        float3 n = f3cross(f3sub(PJ(bs+5), w), f3sub(PJ(bs+17), w));
        float inv = 1.0f / (f3n(n) + 1e-6f);
        n.x *= inv; n.y *= inv; n.z *= inv;
        nh[h] = n;
        o[64 + h*3 + 0] = n.x; o[64 + h*3 + 1] = n.y; o[64 + h*3 + 2] = n.z;
    }

    // ---- spread angles ----
    {
        const int SP[4] = {5, 9, 13, 17};
        #pragma unroll
        for (int h = 0; h < 2; ++h){
            const int bs = h * 21;
            float3 w = h ? w1 : w0;
            #pragma unroll
            for (int i = 0; i < 3; ++i){
                float3 v1 = f3sub(PJ(bs + SP[i]),   w);
                float3 v2 = f3sub(PJ(bs + SP[i+1]), w);
                o[70 + h*3 + i] = ac(f3dot(v1,v2) / (f3n(v1)*f3n(v2) + 1e-6f));
            }
        }
    }

    // ---- normal . up / fwd ----
    o[76] = nh[0].y; o[77] = nh[0].z; o[78] = nh[1].y; o[79] = nh[1].z;

    // ---- velocity (cdiff) ----
    int lo, hi; cidx(t, T, lo, hi);
    float3 vel[2];
    #pragma unroll
    for (int h = 0; h < 2; ++h){
        float3 a = HLD(hi - hb, h), bb = HLD(lo - hb, h);
        vel[h] = make_float3(0.5f*(a.x-bb.x), 0.5f*(a.y-bb.y), 0.5f*(a.z-bb.z));
        float inv = 1.0f / fmaxf(f3n(vel[h]), 1e-6f);
        o[80 + h*3 + 0] = vel[h].x * inv;
        o[80 + h*3 + 1] = vel[h].y * inv;
        o[80 + h*3 + 2] = vel[h].z * inv;
    }

    // ---- velocity angle (pad 0 at t = T-1) ----
    #pragma unroll
    for (int h = 0; h < 2; ++h){
        float val = 0.0f;
        if (t < T - 1){
            float inv1 = 1.0f / (f3n(vel[h]) + 1e-6f);
            int lo2, hi2; cidx(t + 1, T, lo2, hi2);
            float3 a = HLD(hi2 - hb, h), bb = HLD(lo2 - hb, h);
            float3 v2 = make_float3(0.5f*(a.x-bb.x), 0.5f*(a.y-bb.y), 0.5f*(a.z-bb.z));
            float inv2 = 1.0f / (f3n(v2) + 1e-6f);
            val = ac(f3dot(vel[h], v2) * inv1 * inv2);
        }
        o[86 + h] = val;
    }

    // ---- inter-hand ----
    o[88] = fdist(w0, w1);
    {
        float3 rl = f3sub(w1, w0);
        float inv = 1.0f / (f3n(rl) + 1e-6f);
        o[89] = rl.x * inv; o[90] = rl.y * inv;
    }

    // ---- cdiff of dist-to-nose ----
    #pragma unroll
    for (int h = 0; h < 2; ++h){
        float3 ah = HLD(hi - hb, h), an = HLD(hi - hb, 2);
        float3 bh = HLD(lo - hb, h), bn = HLD(lo - hb, 2);
        o[91 + h] = 0.5f * (f3n(f3sub(ah, an)) - f3n(f3sub(bh, bn)));
    }

    // ---- tip x-diffs ----
    {
        float3 mT0 = PJ(12), rT0 = PJ(16), mT1 = PJ(33), rT1 = PJ(37);
        o[93] = iT0.x - mT0.x; o[94] = mT0.x - rT0.x;
        o[95] = iT1.x - mT1.x; o[96] = mT1.x - rT1.x;
    }

    // ---- ld.rd, speeds ----
    {
        float i0 = 1.0f / (f3n(vel[0]) + 1e-6f);
        float i1 = 1.0f / (f3n(vel[1]) + 1e-6f);
        o[97] = f3dot(vel[0], vel[1]) * i0 * i1;
        o[98] = f3n(vel[0]); o[99] = f3n(vel[1]);
    }

    // ---- accel = |cdiff(cdiff(p))| ----
    #pragma unroll
    for (int h = 0; h < 2; ++h){
        int l1, h1; cidx(hi, T, l1, h1);
        int l2, h2; cidx(lo, T, l2, h2);
        float3 A = HLD(h1 - hb, h), B = HLD(l1 - hb, h);
        float3 C = HLD(h2 - hb, h), D = HLD(l2 - hb, h);
        float3 chi = make_float3(0.5f*(A.x-B.x), 0.5f*(A.y-B.y), 0.5f*(A.z-B.z));
        float3 clo = make_float3(0.5f*(C.x-D.x), 0.5f*(C.y-D.y), 0.5f*(C.z-D.z));
        float3 acc = make_float3(0.5f*(chi.x-clo.x), 0.5f*(chi.y-clo.y), 0.5f*(chi.z-clo.z));
        o[100 + h] = f3n(acc);
    }

    // ---- proximity sigmoid ----
    {
        float hd = f3n(f3sub(w0, w1));
        o[102] = 1.0f / (1.0f + expf(-5.0f * (0.05f - hd)));
    }

    // ---- body (x bg) ----
    {
        float3 lsh = PJ(45), rsh = PJ(46), lel = PJ(47), rel2 = PJ(48), ul = PJ(49), ll = PJ(50);
        float shmx = 0.5f * (lsh.x + rsh.x);
        float shmy = 0.5f * (lsh.y + rsh.y);
        float shw = fdist(lsh, rsh);
        float invw = 1.0f / (shw + 1e-6f);
        o[103] = (w0.y - shmy) * invw * bg;
        o[104] = (w0.x - shmx) * invw * bg;
        o[105] = fdist(w0, lsh) * bg;
        o[106] = fdist(w0, lel) * bg;
        o[107] = (w1.y - shmy) * invw * bg;
        o[108] = (w1.x - shmx) * invw * bg;
        o[109] = fdist(w1, rsh) * bg;
        o[110] = fdist(w1, rel2) * bg;
        o[111] = shw * bg;
        float3 mo = make_float3(0.5f*(ul.x+ll.x), 0.5f*(ul.y+ll.y), 0.5f*(ul.z+ll.z));
        o[112] = fdist(w0, mo) * bg;
        o[113] = fdist(w1, mo) * bg;
    }
    #undef PJ
    #undef HLD

    // ---- coalesced flush: smem -> gmem as float4 ----
    __syncthreads();
    {
        const float4* s4 = (const float4*)so;
        float4* dst4 = (float4*)(out + ((long long)b * T + t0) * NF);
        const int n4 = SM_OUT / 4;            // 1824
        for (int i = tid; i < n4; i += BT) dst4[i] = s4[i];
    }
}

extern "C" void kernel_launch(void* const* d_in, const int* in_sizes, int n_in,
                              void* d_out, int out_size)
{
    const float* xyz = (const float*)d_in[0];
    const float* fm  = (const float*)d_in[1];
    const float* bm  = (const float*)d_in[2];
    float* out = (float*)d_out;

    const int T = 512;                 // fixed problem shape (B=256, T=512, N=51)
    const int BTtot = in_sizes[1];     // face_mask elements = B*T
    const int blocks = BTtot / BT;     // T % BT == 0, so each block stays within one b

    cudaFuncSetAttribute(geo_kernel, cudaFuncAttributeMaxDynamicSharedMemorySize, SMEM_BYTES);
    geo_kernel<<<blocks, BT, SMEM_BYTES>>>(xyz, fm, bm, out, T);
}

// round 3
// speedup vs baseline: 1.4578x; 1.4578x over previous
#include <cuda_runtime.h>
#include <math.h>

#define BT     64               // frames per block
#define ROLES  4
#define NTHR   (BT * ROLES)     // 256 threads
#define FPF    153              // floats per frame (51 joints * 3)
#define NF     114              // output features
#define HW     9                // halo floats per frame (joints 0,21,42)

#define SM_FR   (BT * FPF)          // 9792 floats
#define SM_HALO ((BT + 4) * HW)     // 612 floats
#define SM_OUT  (BT * NF)           // 7296 floats
#define SMEM_BYTES ((SM_FR + SM_HALO + SM_OUT) * 4)   // 70800 bytes

__device__ __forceinline__ float3 f3sub(float3 a, float3 b){ return make_float3(a.x-b.x, a.y-b.y, a.z-b.z); }
__device__ __forceinline__ float  f3dot(float3 a, float3 b){ return a.x*b.x + a.y*b.y + a.z*b.z; }
__device__ __forceinline__ float3 f3cross(float3 a, float3 b){
    return make_float3(a.y*b.z - a.z*b.y, a.z*b.x - a.x*b.z, a.x*b.y - a.y*b.x);
}
__device__ __forceinline__ float  f3n(float3 a){ return sqrtf(f3dot(a,a)); }
__device__ __forceinline__ float  fdist(float3 a, float3 b){
    float3 d = f3sub(a,b); return sqrtf(f3dot(d,d) + 1e-6f);
}
__device__ __forceinline__ float ac(float c){
    c = fminf(fmaxf(c, -1.0f + 1e-6f), 1.0f - 1e-6f);
    return acosf(c);
}
__device__ __forceinline__ void cidx(int t, int T, int& lo, int& hi){
    if (t == 0)        { lo = 0;     hi = 2;     }
    else if (t == T-1) { lo = T - 3; hi = T - 1; }
    else               { lo = t - 1; hi = t + 1; }
}

extern __shared__ float smem_dyn[];

__global__ void __launch_bounds__(NTHR)
geo_kernel(const float* __restrict__ xyz,
           const float* __restrict__ fmask,
           const float* __restrict__ bmask,
           float* __restrict__ out, int T)
{
    float* sm   = smem_dyn;                 // [BT*FPF]
    float* halo = sm + SM_FR;               // [(BT+4)*HW]
    float* so   = halo + SM_HALO;           // [BT*NF]

    const int tid = threadIdx.x;
    const long long g0 = (long long)blockIdx.x * BT;
    const int b  = (int)(g0 / T);
    const int t0 = (int)(g0 % T);

    // ---- coalesced main load ----
    {
        const float4* src4 = (const float4*)(xyz + ((long long)b * T + t0) * FPF);
        float4* sm4 = (float4*)sm;
        const int n4 = BT * FPF / 4;          // 2448
        for (int i = tid; i < n4; i += NTHR) sm4[i] = src4[i];
    }
    // ---- halo load: joints 0,21,42, frames t0-2 .. t0+BT+1 ----
    {
        const float* fb = xyz + (long long)b * T * FPF;
        for (int i = tid; i < SM_HALO; i += NTHR){
            int f = i / HW, jc = i % HW;
            int s = t0 - 2 + f;
            float v = 0.0f;
            if (s >= 0 && s < T){
                int j = (jc < 3) ? 0 : ((jc < 6) ? 21 : 42);
                v = fb[(long long)s * FPF + j * 3 + (jc % 3)];
            }
            halo[i] = v;
        }
    }
    __syncthreads();

    const int role = tid >> 6;      // 0..3, warp-uniform
    const int fr   = tid & (BT-1);  // frame within block
    const int t    = t0 + fr;
    const int smb  = fr * FPF;
    #define PJ(j) make_float3(sm[smb + (j)*3], sm[smb + (j)*3 + 1], sm[smb + (j)*3 + 2])
    #define HLD(f, w) make_float3(halo[(f)*HW + (w)*3], halo[(f)*HW + (w)*3 + 1], halo[(f)*HW + (w)*3 + 2])
    const int hb = t0 - 2;          // halo frame index = s - hb

    float* o = so + fr * NF;

    if (role < 2){
        // ================= per-hand geometry (role = hand index) =================
        const int h  = role;
        const int bs = h * 21;

        // tips(5), curls(5), cross, d_ti
        {
            float* oo = o + h * 12;
            float3 tT = PJ(bs+4),  iT = PJ(bs+8),  mT = PJ(bs+12), rT = PJ(bs+16), pT = PJ(bs+20);
            oo[0] = fdist(tT,iT); oo[1] = fdist(iT,mT); oo[2] = fdist(mT,rT);
            oo[3] = fdist(rT,pT); oo[4] = fdist(tT,pT);
            float3 tM = PJ(bs+2),  iM = PJ(bs+5),  mM = PJ(bs+9),  rM = PJ(bs+13), pM = PJ(bs+17);
            float3 tI = PJ(bs+3),  iP = PJ(bs+6),  mP = PJ(bs+10), rP = PJ(bs+14), pP = PJ(bs+18);
            oo[5] = fdist(tM,tT) / (fdist(tM,tI) + 1e-4f);
            oo[6] = fdist(iM,iT) / (fdist(iM,iP) + 1e-4f);
            oo[7] = fdist(mM,mT) / (fdist(mM,mP) + 1e-4f);
            oo[8] = fdist(rM,rT) / (fdist(rM,rP) + 1e-4f);
            oo[9] = fdist(pM,pT) / (fdist(pM,pP) + 1e-4f);
            oo[10] = iT.x - mT.x;
            oo[11] = fdist(tT, iM);
        }

        // 15 joint angles
        {
            const int TPp[15] = {0,1,2, 0,5,6, 0,9,10, 0,13,14, 0,17,18};
            const int TJj[15] = {1,2,3, 5,6,7, 9,10,11, 13,14,15, 17,18,19};
            const int TCc[15] = {2,3,4, 6,7,8, 10,11,12, 14,15,16, 18,19,20};
            #pragma unroll
            for (int k = 0; k < 15; ++k){
                float3 pj = PJ(bs + TJj[k]);
                float3 v1 = f3sub(PJ(bs + TPp[k]), pj);
                float3 v2 = f3sub(PJ(bs + TCc[k]), pj);
                o[34 + h*15 + k] = ac(f3dot(v1,v2) / (f3n(v1)*f3n(v2) + 1e-6f));
            }
        }

        // palm normal + projections
        float3 w = PJ(bs);
        {
            float3 n = f3cross(f3sub(PJ(bs+5), w), f3sub(PJ(bs+17), w));
            float inv = 1.0f / (f3n(n) + 1e-6f);
            n.x *= inv; n.y *= inv; n.z *= inv;
            o[64 + h*3 + 0] = n.x; o[64 + h*3 + 1] = n.y; o[64 + h*3 + 2] = n.z;
            o[76 + h*2] = n.y; o[77 + h*2] = n.z;
        }

        // spread angles
        {
            const int SP[4] = {5, 9, 13, 17};
            #pragma unroll
            for (int i = 0; i < 3; ++i){
                float3 v1 = f3sub(PJ(bs + SP[i]),   w);
                float3 v2 = f3sub(PJ(bs + SP[i+1]), w);
                o[70 + h*3 + i] = ac(f3dot(v1,v2) / (f3n(v1)*f3n(v2) + 1e-6f));
            }
        }
    }
    else if (role == 2){
        // ================= face / body / static inter-hand =================
        const float fg = fmask[(long long)b * T + t];
        const float bg = bmask[(long long)b * T + t];

        float3 w0 = PJ(0), w1 = PJ(21), nose = PJ(42), chin = PJ(43), fh = PJ(44);
        float3 iT0 = PJ(8), iT1 = PJ(29);

        o[24] = fdist(w0,nose)*fg;  o[25] = fdist(w0,chin)*fg;  o[26] = fdist(w0,fh)*fg;
        o[27] = fdist(w1,nose)*fg;  o[28] = fdist(w1,chin)*fg;  o[29] = fdist(w1,fh)*fg;
        o[30] = fdist(iT0,nose)*fg; o[31] = fdist(iT0,fh)*fg;
        o[32] = fdist(iT1,nose)*fg; o[33] = fdist(iT1,fh)*fg;

        // inter-hand
        o[88] = fdist(w0, w1);
        {
            float3 rl = f3sub(w1, w0);
            float inv = 1.0f / (f3n(rl) + 1e-6f);
            o[89] = rl.x * inv; o[90] = rl.y * inv;
        }

        // tip x-diffs
        {
            float3 mT0 = PJ(12), rT0 = PJ(16), mT1 = PJ(33), rT1 = PJ(37);
            o[93] = iT0.x - mT0.x; o[94] = mT0.x - rT0.x;
            o[95] = iT1.x - mT1.x; o[96] = mT1.x - rT1.x;
        }

        // proximity sigmoid
        {
            float hd = f3n(f3sub(w0, w1));
            o[102] = 1.0f / (1.0f + expf(-5.0f * (0.05f - hd)));
        }

        // body (x bg)
        {
            float3 lsh = PJ(45), rsh = PJ(46), lel = PJ(47), rel2 = PJ(48), ul = PJ(49), ll = PJ(50);
            float shmx = 0.5f * (lsh.x + rsh.x);
            float shmy = 0.5f * (lsh.y + rsh.y);
            float shw = fdist(lsh, rsh);
            float invw = 1.0f / (shw + 1e-6f);
            o[103] = (w0.y - shmy) * invw * bg;
            o[104] = (w0.x - shmx) * invw * bg;
            o[105] = fdist(w0, lsh) * bg;
            o[106] = fdist(w0, lel) * bg;
            o[107] = (w1.y - shmy) * invw * bg;
            o[108] = (w1.x - shmx) * invw * bg;
            o[109] = fdist(w1, rsh) * bg;
            o[110] = fdist(w1, rel2) * bg;
            o[111] = shw * bg;
            float3 mo = make_float3(0.5f*(ul.x+ll.x), 0.5f*(ul.y+ll.y), 0.5f*(ul.z+ll.z));
            o[112] = fdist(w0, mo) * bg;
            o[113] = fdist(w1, mo) * bg;
        }
    }
    else {
        // ================= temporal features =================
        int lo, hi; cidx(t, T, lo, hi);
        float3 vel[2];
        #pragma unroll
        for (int h = 0; h < 2; ++h){
            float3 a = HLD(hi - hb, h), bb = HLD(lo - hb, h);
            vel[h] = make_float3(0.5f*(a.x-bb.x), 0.5f*(a.y-bb.y), 0.5f*(a.z-bb.z));
            float inv = 1.0f / fmaxf(f3n(vel[h]), 1e-6f);
            o[80 + h*3 + 0] = vel[h].x * inv;
            o[80 + h*3 + 1] = vel[h].y * inv;
            o[80 + h*3 + 2] = vel[h].z * inv;
        }

        // velocity angle (pad 0 at t = T-1)
        #pragma unroll
        for (int h = 0; h < 2; ++h){
            float val = 0.0f;
            if (t < T - 1){
                float inv1 = 1.0f / (f3n(vel[h]) + 1e-6f);
                int lo2, hi2; cidx(t + 1, T, lo2, hi2);
                float3 a = HLD(hi2 - hb, h), bb = HLD(lo2 - hb, h);
                float3 v2 = make_float3(0.5f*(a.x-bb.x), 0.5f*(a.y-bb.y), 0.5f*(a.z-bb.z));
                float inv2 = 1.0f / (f3n(v2) + 1e-6f);
                val = ac(f3dot(vel[h], v2) * inv1 * inv2);
            }
            o[86 + h] = val;
        }

        // cdiff of dist-to-nose
        #pragma unroll
        for (int h = 0; h < 2; ++h){
            float3 ah = HLD(hi - hb, h), an = HLD(hi - hb, 2);
            float3 bh = HLD(lo - hb, h), bn = HLD(lo - hb, 2);
            o[91 + h] = 0.5f * (f3n(f3sub(ah, an)) - f3n(f3sub(bh, bn)));
        }

        // ld.rd, speeds
        {
            float i0 = 1.0f / (f3n(vel[0]) + 1e-6f);
            float i1 = 1.0f / (f3n(vel[1]) + 1e-6f);
            o[97] = f3dot(vel[0], vel[1]) * i0 * i1;
            o[98] = f3n(vel[0]); o[99] = f3n(vel[1]);
        }

        // accel = |cdiff(cdiff(p))|
        #pragma unroll
        for (int h = 0; h < 2; ++h){
            int l1, h1; cidx(hi, T, l1, h1);
            int l2, h2; cidx(lo, T, l2, h2);
            float3 A = HLD(h1 - hb, h), B = HLD(l1 - hb, h);
            float3 C = HLD(h2 - hb, h), D = HLD(l2 - hb, h);
            float3 chi = make_float3(0.5f*(A.x-B.x), 0.5f*(A.y-B.y), 0.5f*(A.z-B.z));
            float3 clo = make_float3(0.5f*(C.x-D.x), 0.5f*(C.y-D.y), 0.5f*(C.z-D.z));
            float3 acc = make_float3(0.5f*(chi.x-clo.x), 0.5f*(chi.y-clo.y), 0.5f*(chi.z-clo.z));
            o[100 + h] = f3n(acc);
        }
    }
    #undef PJ
    #undef HLD

    // ---- coalesced flush: smem -> gmem as float4 ----
    __syncthreads();
    {
        const float4* s4 = (const float4*)so;
        float4* dst4 = (float4*)(out + ((long long)b * T + t0) * NF);
        const int n4 = SM_OUT / 4;            // 1824
        for (int i = tid; i < n4; i += NTHR) dst4[i] = s4[i];
    }
}

extern "C" void kernel_launch(void* const* d_in, const int* in_sizes, int n_in,
                              void* d_out, int out_size)
{
    const float* xyz = (const float*)d_in[0];
    const float* fm  = (const float*)d_in[1];
    const float* bm  = (const float*)d_in[2];
    float* out = (float*)d_out;

    const int T = 512;                 // fixed problem shape (B=256, T=512, N=51)
    const int BTtot = in_sizes[1];     // face_mask elements = B*T
    const int blocks = BTtot / BT;     // each block stays within one b (T % BT == 0)

    cudaFuncSetAttribute(geo_kernel, cudaFuncAttributeMaxDynamicSharedMemorySize, SMEM_BYTES);
    geo_kernel<<<blocks, NTHR, SMEM_BYTES>>>(xyz, fm, bm, out, T);
}

// round 4
// speedup vs baseline: 1.6394x; 1.1246x over previous
#include <cuda_runtime.h>
#include <math.h>

#define BT     32               // frames per block
#define ROLES  8
#define NTHR   (BT * ROLES)     // 256 threads
#define FPF    153              // floats per frame (51 joints * 3)
#define NF     114              // output features
#define HW     9                // halo floats per frame (joints 0,21,42)

#define SM_FR   (BT * FPF)          // 4896 floats
#define SM_HALO ((BT + 4) * HW)     // 324 floats
#define SM_OUT  (BT * NF)           // 3648 floats
#define SMEM_BYTES ((SM_FR + SM_HALO + SM_OUT) * 4)   // 35472 bytes

__device__ __forceinline__ float3 f3sub(float3 a, float3 b){ return make_float3(a.x-b.x, a.y-b.y, a.z-b.z); }
__device__ __forceinline__ float  f3dot(float3 a, float3 b){ return a.x*b.x + a.y*b.y + a.z*b.z; }
__device__ __forceinline__ float3 f3cross(float3 a, float3 b){
    return make_float3(a.y*b.z - a.z*b.y, a.z*b.x - a.x*b.z, a.x*b.y - a.y*b.x);
}
__device__ __forceinline__ float  f3n(float3 a){ return sqrtf(f3dot(a,a)); }
__device__ __forceinline__ float  fdist(float3 a, float3 b){
    float3 d = f3sub(a,b); return sqrtf(f3dot(d,d) + 1e-6f);
}
__device__ __forceinline__ float ac(float c){
    c = fminf(fmaxf(c, -1.0f + 1e-6f), 1.0f - 1e-6f);
    return acosf(c);
}
__device__ __forceinline__ void cidx(int t, int T, int& lo, int& hi){
    if (t == 0)        { lo = 0;     hi = 2;     }
    else if (t == T-1) { lo = T - 3; hi = T - 1; }
    else               { lo = t - 1; hi = t + 1; }
}

extern __shared__ float smem_dyn[];

__global__ void __launch_bounds__(NTHR, 5)
geo_kernel(const float* __restrict__ xyz,
           const float* __restrict__ fmask,
           const float* __restrict__ bmask,
           float* __restrict__ out, int T)
{
    float* sm   = smem_dyn;                 // [BT*FPF]
    float* halo = sm + SM_FR;               // [(BT+4)*HW]
    float* so   = halo + SM_HALO;           // [BT*NF]

    const int tid = threadIdx.x;
    const long long g0 = (long long)blockIdx.x * BT;
    const int b  = (int)(g0 / T);
    const int t0 = (int)(g0 % T);

    // ---- coalesced main load ----
    {
        const float4* src4 = (const float4*)(xyz + ((long long)b * T + t0) * FPF);
        float4* sm4 = (float4*)sm;
        const int n4 = BT * FPF / 4;          // 1224
        for (int i = tid; i < n4; i += NTHR) sm4[i] = src4[i];
    }
    // ---- halo load: joints 0,21,42, frames t0-2 .. t0+BT+1 ----
    {
        const float* fb = xyz + (long long)b * T * FPF;
        for (int i = tid; i < SM_HALO; i += NTHR){
            int f = i / HW, jc = i % HW;
            int s = t0 - 2 + f;
            float v = 0.0f;
            if (s >= 0 && s < T){
                int j = (jc < 3) ? 0 : ((jc < 6) ? 21 : 42);
                v = fb[(long long)s * FPF + j * 3 + (jc % 3)];
            }
            halo[i] = v;
        }
    }
    __syncthreads();

    const int role = tid >> 5;      // 0..7, one warp per role
    const int fr   = tid & (BT-1);  // frame within block
    const int t    = t0 + fr;
    const int smb  = fr * FPF;
    #define PJ(j) make_float3(sm[smb + (j)*3], sm[smb + (j)*3 + 1], sm[smb + (j)*3 + 2])
    #define HLD(f, w) make_float3(halo[(f)*HW + (w)*3], halo[(f)*HW + (w)*3 + 1], halo[(f)*HW + (w)*3 + 2])
    const int hb = t0 - 2;          // halo frame index = s - hb

    float* o = so + fr * NF;

    if (role < 4){
        const int h  = role >> 1;       // hand index
        const int bs = h * 21;

        if ((role & 1) == 0){
            // ---- hand distances: tips(5), curls(5), cross, d_ti ----
            {
                float* oo = o + h * 12;
                float3 tT = PJ(bs+4),  iT = PJ(bs+8),  mT = PJ(bs+12), rT = PJ(bs+16), pT = PJ(bs+20);
                oo[0] = fdist(tT,iT); oo[1] = fdist(iT,mT); oo[2] = fdist(mT,rT);
                oo[3] = fdist(rT,pT); oo[4] = fdist(tT,pT);
                float3 tM = PJ(bs+2),  iM = PJ(bs+5),  mM = PJ(bs+9),  rM = PJ(bs+13), pM = PJ(bs+17);
                float3 tI = PJ(bs+3),  iP = PJ(bs+6),  mP = PJ(bs+10), rP = PJ(bs+14), pP = PJ(bs+18);
                oo[5] = fdist(tM,tT) / (fdist(tM,tI) + 1e-4f);
                oo[6] = fdist(iM,iT) / (fdist(iM,iP) + 1e-4f);
                oo[7] = fdist(mM,mT) / (fdist(mM,mP) + 1e-4f);
                oo[8] = fdist(rM,rT) / (fdist(rM,rP) + 1e-4f);
                oo[9] = fdist(pM,pT) / (fdist(pM,pP) + 1e-4f);
                oo[10] = iT.x - mT.x;
                oo[11] = fdist(tT, iM);
            }
            // ---- palm normal + projections ----
            float3 w = PJ(bs);
            {
                float3 n = f3cross(f3sub(PJ(bs+5), w), f3sub(PJ(bs+17), w));
                float inv = 1.0f / (f3n(n) + 1e-6f);
                n.x *= inv; n.y *= inv; n.z *= inv;
                o[64 + h*3 + 0] = n.x; o[64 + h*3 + 1] = n.y; o[64 + h*3 + 2] = n.z;
                o[76 + h*2] = n.y; o[77 + h*2] = n.z;
            }
            // ---- spread angles ----
            {
                const int SP[4] = {5, 9, 13, 17};
                #pragma unroll
                for (int i = 0; i < 3; ++i){
                    float3 v1 = f3sub(PJ(bs + SP[i]),   w);
                    float3 v2 = f3sub(PJ(bs + SP[i+1]), w);
                    o[70 + h*3 + i] = ac(f3dot(v1,v2) / (f3n(v1)*f3n(v2) + 1e-6f));
                }
            }
        } else {
            // ---- 15 joint angles ----
            const int TPp[15] = {0,1,2, 0,5,6, 0,9,10, 0,13,14, 0,17,18};
            const int TJj[15] = {1,2,3, 5,6,7, 9,10,11, 13,14,15, 17,18,19};
            const int TCc[15] = {2,3,4, 6,7,8, 10,11,12, 14,15,16, 18,19,20};
            #pragma unroll
            for (int k = 0; k < 15; ++k){
                float3 pj = PJ(bs + TJj[k]);
                float3 v1 = f3sub(PJ(bs + TPp[k]), pj);
                float3 v2 = f3sub(PJ(bs + TCc[k]), pj);
                o[34 + h*15 + k] = ac(f3dot(v1,v2) / (f3n(v1)*f3n(v2) + 1e-6f));
            }
        }
    }
    else if (role == 4){
        // ---- face (x fg) ----
        const float fg = fmask[(long long)b * T + t];
        float3 w0 = PJ(0), w1 = PJ(21), nose = PJ(42), chin = PJ(43), fh = PJ(44);
        float3 iT0 = PJ(8), iT1 = PJ(29);
        o[24] = fdist(w0,nose)*fg;  o[25] = fdist(w0,chin)*fg;  o[26] = fdist(w0,fh)*fg;
        o[27] = fdist(w1,nose)*fg;  o[28] = fdist(w1,chin)*fg;  o[29] = fdist(w1,fh)*fg;
        o[30] = fdist(iT0,nose)*fg; o[31] = fdist(iT0,fh)*fg;
        o[32] = fdist(iT1,nose)*fg; o[33] = fdist(iT1,fh)*fg;
    }
    else if (role == 5){
        // ---- body / static inter-hand ----
        const float bg = bmask[(long long)b * T + t];
        float3 w0 = PJ(0), w1 = PJ(21);
        float3 iT0 = PJ(8), iT1 = PJ(29);

        o[88] = fdist(w0, w1);
        {
            float3 rl = f3sub(w1, w0);
            float inv = 1.0f / (f3n(rl) + 1e-6f);
            o[89] = rl.x * inv; o[90] = rl.y * inv;
        }
        {
            float3 mT0 = PJ(12), rT0 = PJ(16), mT1 = PJ(33), rT1 = PJ(37);
            o[93] = iT0.x - mT0.x; o[94] = mT0.x - rT0.x;
            o[95] = iT1.x - mT1.x; o[96] = mT1.x - rT1.x;
        }
        {
            float hd = f3n(f3sub(w0, w1));
            o[102] = 1.0f / (1.0f + expf(-5.0f * (0.05f - hd)));
        }
        {
            float3 lsh = PJ(45), rsh = PJ(46), lel = PJ(47), rel2 = PJ(48), ul = PJ(49), ll = PJ(50);
            float shmx = 0.5f * (lsh.x + rsh.x);
            float shmy = 0.5f * (lsh.y + rsh.y);
            float shw = fdist(lsh, rsh);
            float invw = 1.0f / (shw + 1e-6f);
            o[103] = (w0.y - shmy) * invw * bg;
            o[104] = (w0.x - shmx) * invw * bg;
            o[105] = fdist(w0, lsh) * bg;
            o[106] = fdist(w0, lel) * bg;
            o[107] = (w1.y - shmy) * invw * bg;
            o[108] = (w1.x - shmx) * invw * bg;
            o[109] = fdist(w1, rsh) * bg;
            o[110] = fdist(w1, rel2) * bg;
            o[111] = shw * bg;
            float3 mo = make_float3(0.5f*(ul.x+ll.x), 0.5f*(ul.y+ll.y), 0.5f*(ul.z+ll.z));
            o[112] = fdist(w0, mo) * bg;
            o[113] = fdist(w1, mo) * bg;
        }
    }
    else if (role == 6){
        // ---- temporal A: vel dirs, vel angle, nose-dist cdiff ----
        int lo, hi; cidx(t, T, lo, hi);
        float3 vel[2];
        #pragma unroll
        for (int h = 0; h < 2; ++h){
            float3 a = HLD(hi - hb, h), bb = HLD(lo - hb, h);
            vel[h] = make_float3(0.5f*(a.x-bb.x), 0.5f*(a.y-bb.y), 0.5f*(a.z-bb.z));
            float inv = 1.0f / fmaxf(f3n(vel[h]), 1e-6f);
            o[80 + h*3 + 0] = vel[h].x * inv;
            o[80 + h*3 + 1] = vel[h].y * inv;
            o[80 + h*3 + 2] = vel[h].z * inv;
        }
        #pragma unroll
        for (int h = 0; h < 2; ++h){
            float val = 0.0f;
            if (t < T - 1){
                float inv1 = 1.0f / (f3n(vel[h]) + 1e-6f);
                int lo2, hi2; cidx(t + 1, T, lo2, hi2);
                float3 a = HLD(hi2 - hb, h), bb = HLD(lo2 - hb, h);
                float3 v2 = make_float3(0.5f*(a.x-bb.x), 0.5f*(a.y-bb.y), 0.5f*(a.z-bb.z));
                float inv2 = 1.0f / (f3n(v2) + 1e-6f);
                val = ac(f3dot(vel[h], v2) * inv1 * inv2);
            }
            o[86 + h] = val;
        }
        #pragma unroll
        for (int h = 0; h < 2; ++h){
            float3 ah = HLD(hi - hb, h), an = HLD(hi - hb, 2);
            float3 bh = HLD(lo - hb, h), bn = HLD(lo - hb, 2);
            o[91 + h] = 0.5f * (f3n(f3sub(ah, an)) - f3n(f3sub(bh, bn)));
        }
    }
    else {
        // ---- temporal B: ld.rd, speeds, accel ----
        int lo, hi; cidx(t, T, lo, hi);
        float3 vel[2];
        #pragma unroll
        for (int h = 0; h < 2; ++h){
            float3 a = HLD(hi - hb, h), bb = HLD(lo - hb, h);
            vel[h] = make_float3(0.5f*(a.x-bb.x), 0.5f*(a.y-bb.y), 0.5f*(a.z-bb.z));
        }
        {
            float i0 = 1.0f / (f3n(vel[0]) + 1e-6f);
            float i1 = 1.0f / (f3n(vel[1]) + 1e-6f);
            o[97] = f3dot(vel[0], vel[1]) * i0 * i1;
            o[98] = f3n(vel[0]); o[99] = f3n(vel[1]);
        }
        #pragma unroll
        for (int h = 0; h < 2; ++h){
            int l1, h1; cidx(hi, T, l1, h1);
            int l2, h2; cidx(lo, T, l2, h2);
            float3 A = HLD(h1 - hb, h), B = HLD(l1 - hb, h);
            float3 C = HLD(h2 - hb, h), D = HLD(l2 - hb, h);
            float3 chi = make_float3(0.5f*(A.x-B.x), 0.5f*(A.y-B.y), 0.5f*(A.z-B.z));
            float3 clo = make_float3(0.5f*(C.x-D.x), 0.5f*(C.y-D.y), 0.5f*(C.z-D.z));
            float3 acc = make_float3(0.5f*(chi.x-clo.x), 0.5f*(chi.y-clo.y), 0.5f*(chi.z-clo.z));
            o[100 + h] = f3n(acc);
        }
    }
    #undef PJ
    #undef HLD

    // ---- coalesced flush: smem -> gmem as float4 ----
    __syncthreads();
    {
        const float4* s4 = (const float4*)so;
        float4* dst4 = (float4*)(out + ((long long)b * T + t0) * NF);
        const int n4 = SM_OUT / 4;            // 912
        for (int i = tid; i < n4; i += NTHR) dst4[i] = s4[i];
    }
}

extern "C" void kernel_launch(void* const* d_in, const int* in_sizes, int n_in,
                              void* d_out, int out_size)
{
    const float* xyz = (const float*)d_in[0];
    const float* fm  = (const float*)d_in[1];
    const float* bm  = (const float*)d_in[2];
    float* out = (float*)d_out;

    const int T = 512;                 // fixed problem shape (B=256, T=512, N=51)
    const int BTtot = in_sizes[1];     // face_mask elements = B*T
    const int blocks = BTtot / BT;     // each block stays within one b (T % BT == 0)

    cudaFuncSetAttribute(geo_kernel, cudaFuncAttributeMaxDynamicSharedMemorySize, SMEM_BYTES);
    geo_kernel<<<blocks, NTHR, SMEM_BYTES>>>(xyz, fm, bm, out, T);
}

// round 5
// speedup vs baseline: 2.2728x; 1.3864x over previous
#include <cuda_runtime.h>
#include <math.h>

#define BT     32               // frames per block
#define NTHR   256              // 8 warps, one role each
#define FPF    153
#define NF     114
#define HW     9

#define SM_FR   (BT * FPF)          // 4896 floats
#define SM_HALO ((BT + 4) * HW)     // 324 floats
#define SM_OUT  (BT * NF)           // 3648 floats
#define SMEM_BYTES ((SM_FR + SM_HALO + SM_OUT) * 4)   // 35472 bytes

// fast sqrt of non-negative x (0-safe): x * rsqrt(x)
__device__ __forceinline__ float fsq(float x){
    return x * rsqrtf(fmaxf(x, 1e-38f));
}
__device__ __forceinline__ float3 f3sub(float3 a, float3 b){ return make_float3(a.x-b.x, a.y-b.y, a.z-b.z); }
__device__ __forceinline__ float  f3dot(float3 a, float3 b){ return a.x*b.x + a.y*b.y + a.z*b.z; }
__device__ __forceinline__ float3 f3cross(float3 a, float3 b){
    return make_float3(a.y*b.z - a.z*b.y, a.z*b.x - a.x*b.z, a.x*b.y - a.y*b.x);
}
__device__ __forceinline__ float  f3n(float3 a){ return fsq(f3dot(a,a)); }
__device__ __forceinline__ float  fdist(float3 a, float3 b){
    float3 d = f3sub(a,b);
    float q = f3dot(d,d) + 1e-6f;       // >= 1e-6 > 0
    return q * rsqrtf(q);
}
// acos via A&S 4.4.46 8-term poly, |eps| <= 2e-8 (input pre-clamped)
__device__ __forceinline__ float ac(float c){
    c = fminf(fmaxf(c, -1.0f + 1e-6f), 1.0f - 1e-6f);
    float xa = fabsf(c);
    float p =            -0.0012624911f;
    p = fmaf(p, xa,  0.0066700901f);
    p = fmaf(p, xa, -0.0170881256f);
    p = fmaf(p, xa,  0.0308918810f);
    p = fmaf(p, xa, -0.0501743046f);
    p = fmaf(p, xa,  0.0889789874f);
    p = fmaf(p, xa, -0.2145988016f);
    p = fmaf(p, xa,  1.5707963050f);
    float s = 1.0f - xa;                // >= 1e-6
    s = s * rsqrtf(s);
    float r = p * s;
    return (c < 0.0f) ? (3.14159265358979f - r) : r;
}
__device__ __forceinline__ float jangle(float3 P, float3 J, float3 C){
    float3 v1 = f3sub(P, J), v2 = f3sub(C, J);
    float d12 = f3dot(v1, v2);
    float nn  = fsq(f3dot(v1,v1) * f3dot(v2,v2));   // = |v1||v2| up to rounding
    return ac(__fdividef(d12, nn + 1e-6f));
}
__device__ __forceinline__ void cidx(int t, int T, int& lo, int& hi){
    if (t == 0)        { lo = 0;     hi = 2;     }
    else if (t == T-1) { lo = T - 3; hi = T - 1; }
    else               { lo = t - 1; hi = t + 1; }
}

extern __shared__ float smem_dyn[];

__global__ void __launch_bounds__(NTHR, 6)
geo_kernel(const float* __restrict__ xyz,
           const float* __restrict__ fmask,
           const float* __restrict__ bmask,
           float* __restrict__ out, int T)
{
    float* sm   = smem_dyn;                 // [BT*FPF]
    float* halo = sm + SM_FR;               // [(BT+4)*HW]
    float* so   = halo + SM_HALO;           // [BT*NF]

    const int tid = threadIdx.x;
    const long long g0 = (long long)blockIdx.x * BT;
    const int b  = (int)(g0 / T);
    const int t0 = (int)(g0 % T);

    // ---- coalesced main load ----
    {
        const float4* src4 = (const float4*)(xyz + ((long long)b * T + t0) * FPF);
        float4* sm4 = (float4*)sm;
        const int n4 = BT * FPF / 4;          // 1224
        for (int i = tid; i < n4; i += NTHR) sm4[i] = src4[i];
    }
    // ---- halo: joints 0,21,42 for frames t0-2 .. t0+BT+1 ----
    {
        const float* fb = xyz + (long long)b * T * FPF;
        for (int i = tid; i < SM_HALO; i += NTHR){
            int f = i / HW, jc = i % HW;
            int s = t0 - 2 + f;
            float v = 0.0f;
            if (s >= 0 && s < T){
                int j = (jc < 3) ? 0 : ((jc < 6) ? 21 : 42);
                v = fb[(long long)s * FPF + j * 3 + (jc % 3)];
            }
            halo[i] = v;
        }
    }
    __syncthreads();

    const int role = tid >> 5;      // 0..7, one warp per role
    const int fr   = tid & 31;      // frame within block
    const int t    = t0 + fr;
    const int smb  = fr * FPF;
    #define PJ(j) make_float3(sm[smb + (j)*3], sm[smb + (j)*3 + 1], sm[smb + (j)*3 + 2])
    #define HLD(f, w) make_float3(halo[(f)*HW + (w)*3], halo[(f)*HW + (w)*3 + 1], halo[(f)*HW + (w)*3 + 2])
    const int hb = t0 - 2;

    float* o = so + fr * NF;

    static const int TPp[15] = {0,1,2, 0,5,6, 0,9,10, 0,13,14, 0,17,18};
    static const int TJj[15] = {1,2,3, 5,6,7, 9,10,11, 13,14,15, 17,18,19};
    static const int TCc[15] = {2,3,4, 6,7,8, 10,11,12, 14,15,16, 18,19,20};

    if (role == 0 || role == 2){
        // ======= hand dists + normal + spread (h = role>>1) =======
        const int h  = role >> 1;
        const int bs = h * 21;
        {
            float* oo = o + h * 12;
            float3 tT = PJ(bs+4),  iT = PJ(bs+8),  mT = PJ(bs+12), rT = PJ(bs+16), pT = PJ(bs+20);
            oo[0] = fdist(tT,iT); oo[1] = fdist(iT,mT); oo[2] = fdist(mT,rT);
            oo[3] = fdist(rT,pT); oo[4] = fdist(tT,pT);
            float3 tM = PJ(bs+2),  iM = PJ(bs+5),  mM = PJ(bs+9),  rM = PJ(bs+13), pM = PJ(bs+17);
            float3 tI = PJ(bs+3),  iP = PJ(bs+6),  mP = PJ(bs+10), rP = PJ(bs+14), pP = PJ(bs+18);
            oo[5] = __fdividef(fdist(tM,tT), fdist(tM,tI) + 1e-4f);
            oo[6] = __fdividef(fdist(iM,iT), fdist(iM,iP) + 1e-4f);
            oo[7] = __fdividef(fdist(mM,mT), fdist(mM,mP) + 1e-4f);
            oo[8] = __fdividef(fdist(rM,rT), fdist(rM,rP) + 1e-4f);
            oo[9] = __fdividef(fdist(pM,pT), fdist(pM,pP) + 1e-4f);
            oo[10] = iT.x - mT.x;
            oo[11] = fdist(tT, iM);
        }
        float3 w = PJ(bs);
        {
            float3 n = f3cross(f3sub(PJ(bs+5), w), f3sub(PJ(bs+17), w));
            float inv = __fdividef(1.0f, f3n(n) + 1e-6f);
            n.x *= inv; n.y *= inv; n.z *= inv;
            o[64 + h*3 + 0] = n.x; o[64 + h*3 + 1] = n.y; o[64 + h*3 + 2] = n.z;
            o[76 + h*2] = n.y; o[77 + h*2] = n.z;
        }
        {
            const int SP[4] = {5, 9, 13, 17};
            #pragma unroll
            for (int i = 0; i < 3; ++i){
                float3 v1 = f3sub(PJ(bs + SP[i]),   w);
                float3 v2 = f3sub(PJ(bs + SP[i+1]), w);
                float nn = fsq(f3dot(v1,v1) * f3dot(v2,v2));
                o[70 + h*3 + i] = ac(__fdividef(f3dot(v1,v2), nn + 1e-6f));
            }
        }
    }
    else if (role == 1 || role == 3){
        // ======= angles k=0..7 (h = (role-1)>>1) =======
        const int h  = (role - 1) >> 1;
        const int bs = h * 21;
        #pragma unroll
        for (int k = 0; k < 8; ++k)
            o[34 + h*15 + k] = jangle(PJ(bs + TPp[k]), PJ(bs + TJj[k]), PJ(bs + TCc[k]));
    }
    else if (role == 4 || role == 5){
        // ======= angles k=8..14 (h = role-4) =======
        const int h  = role - 4;
        const int bs = h * 21;
        #pragma unroll
        for (int k = 8; k < 15; ++k)
            o[34 + h*15 + k] = jangle(PJ(bs + TPp[k]), PJ(bs + TJj[k]), PJ(bs + TCc[k]));
    }
    else if (role == 6){
        // ======= face (x fg) + velocity dirs + velocity angles =======
        const float fg = fmask[(long long)b * T + t];
        float3 w0 = PJ(0), w1 = PJ(21), nose = PJ(42), chin = PJ(43), fh = PJ(44);
        float3 iT0 = PJ(8), iT1 = PJ(29);
        o[24] = fdist(w0,nose)*fg;  o[25] = fdist(w0,chin)*fg;  o[26] = fdist(w0,fh)*fg;
        o[27] = fdist(w1,nose)*fg;  o[28] = fdist(w1,chin)*fg;  o[29] = fdist(w1,fh)*fg;
        o[30] = fdist(iT0,nose)*fg; o[31] = fdist(iT0,fh)*fg;
        o[32] = fdist(iT1,nose)*fg; o[33] = fdist(iT1,fh)*fg;

        int lo, hi; cidx(t, T, lo, hi);
        #pragma unroll
        for (int h = 0; h < 2; ++h){
            float3 a = HLD(hi - hb, h), bb = HLD(lo - hb, h);
            float3 vel = make_float3(0.5f*(a.x-bb.x), 0.5f*(a.y-bb.y), 0.5f*(a.z-bb.z));
            float inv = __fdividef(1.0f, fmaxf(f3n(vel), 1e-6f));
            o[80 + h*3 + 0] = vel.x * inv;
            o[80 + h*3 + 1] = vel.y * inv;
            o[80 + h*3 + 2] = vel.z * inv;

            float val = 0.0f;
            if (t < T - 1){
                int lo2, hi2; cidx(t + 1, T, lo2, hi2);
                float3 a2 = HLD(hi2 - hb, h), b2 = HLD(lo2 - hb, h);
                float3 v2 = make_float3(0.5f*(a2.x-b2.x), 0.5f*(a2.y-b2.y), 0.5f*(a2.z-b2.z));
                float inv1 = __fdividef(1.0f, f3n(vel) + 1e-6f);
                float inv2 = __fdividef(1.0f, f3n(v2)  + 1e-6f);
                val = ac(f3dot(vel, v2) * inv1 * inv2);
            }
            o[86 + h] = val;
        }
    }
    else {
        // ======= role 7: misc temporal + inter-hand + body =======
        const float bg = bmask[(long long)b * T + t];
        float3 w0 = PJ(0), w1 = PJ(21);
        float3 iT0 = PJ(8), iT1 = PJ(29);

        o[88] = fdist(w0, w1);
        {
            float3 rl = f3sub(w1, w0);
            float inv = __fdividef(1.0f, f3n(rl) + 1e-6f);
            o[89] = rl.x * inv; o[90] = rl.y * inv;
        }
        int lo, hi; cidx(t, T, lo, hi);
        // cdiff of dist-to-nose
        #pragma unroll
        for (int h = 0; h < 2; ++h){
            float3 ah = HLD(hi - hb, h), an = HLD(hi - hb, 2);
            float3 bh = HLD(lo - hb, h), bn = HLD(lo - hb, 2);
            o[91 + h] = 0.5f * (f3n(f3sub(ah, an)) - f3n(f3sub(bh, bn)));
        }
        {
            float3 mT0 = PJ(12), rT0 = PJ(16), mT1 = PJ(33), rT1 = PJ(37);
            o[93] = iT0.x - mT0.x; o[94] = mT0.x - rT0.x;
            o[95] = iT1.x - mT1.x; o[96] = mT1.x - rT1.x;
        }
        // velocities: ld.rd, speeds
        float3 vel[2];
        #pragma unroll
        for (int h = 0; h < 2; ++h){
            float3 a = HLD(hi - hb, h), bb = HLD(lo - hb, h);
            vel[h] = make_float3(0.5f*(a.x-bb.x), 0.5f*(a.y-bb.y), 0.5f*(a.z-bb.z));
        }
        {
            float i0 = __fdividef(1.0f, f3n(vel[0]) + 1e-6f);
            float i1 = __fdividef(1.0f, f3n(vel[1]) + 1e-6f);
            o[97] = f3dot(vel[0], vel[1]) * i0 * i1;
            o[98] = f3n(vel[0]); o[99] = f3n(vel[1]);
        }
        // accel
        #pragma unroll
        for (int h = 0; h < 2; ++h){
            int l1, h1; cidx(hi, T, l1, h1);
            int l2, h2; cidx(lo, T, l2, h2);
            float3 A = HLD(h1 - hb, h), B = HLD(l1 - hb, h);
            float3 C = HLD(h2 - hb, h), D = HLD(l2 - hb, h);
            float3 chi = make_float3(0.5f*(A.x-B.x), 0.5f*(A.y-B.y), 0.5f*(A.z-B.z));
            float3 clo = make_float3(0.5f*(C.x-D.x), 0.5f*(C.y-D.y), 0.5f*(C.z-D.z));
            float3 acc = make_float3(0.5f*(chi.x-clo.x), 0.5f*(chi.y-clo.y), 0.5f*(chi.z-clo.z));
            o[100 + h] = f3n(acc);
        }
        // proximity sigmoid
        {
            float hd = f3n(f3sub(w0, w1));
            o[102] = __fdividef(1.0f, 1.0f + __expf(-5.0f * (0.05f - hd)));
        }
        // body (x bg)
        {
            float3 lsh = PJ(45), rsh = PJ(46), lel = PJ(47), rel2 = PJ(48), ul = PJ(49), ll = PJ(50);
            float shmx = 0.5f * (lsh.x + rsh.x);
            float shmy = 0.5f * (lsh.y + rsh.y);
            float shw = fdist(lsh, rsh);
            float invw = __fdividef(1.0f, shw + 1e-6f);
            o[103] = (w0.y - shmy) * invw * bg;
            o[104] = (w0.x - shmx) * invw * bg;
            o[105] = fdist(w0, lsh) * bg;
            o[106] = fdist(w0, lel) * bg;
            o[107] = (w1.y - shmy) * invw * bg;
            o[108] = (w1.x - shmx) * invw * bg;
            o[109] = fdist(w1, rsh) * bg;
            o[110] = fdist(w1, rel2) * bg;
            o[111] = shw * bg;
            float3 mo = make_float3(0.5f*(ul.x+ll.x), 0.5f*(ul.y+ll.y), 0.5f*(ul.z+ll.z));
            o[112] = fdist(w0, mo) * bg;
            o[113] = fdist(w1, mo) * bg;
        }
    }
    #undef PJ
    #undef HLD

    // ---- coalesced flush ----
    __syncthreads();
    {
        const float4* s4 = (const float4*)so;
        float4* dst4 = (float4*)(out + ((long long)b * T + t0) * NF);
        const int n4 = SM_OUT / 4;            // 912
        for (int i = tid; i < n4; i += NTHR) dst4[i] = s4[i];
    }
}

extern "C" void kernel_launch(void* const* d_in, const int* in_sizes, int n_in,
                              void* d_out, int out_size)
{
    const float* xyz = (const float*)d_in[0];
    const float* fm  = (const float*)d_in[1];
    const float* bm  = (const float*)d_in[2];
    float* out = (float*)d_out;

    const int T = 512;
    const int BTtot = in_sizes[1];     // B*T
    const int blocks = BTtot / BT;

    cudaFuncSetAttribute(geo_kernel, cudaFuncAttributeMaxDynamicSharedMemorySize, SMEM_BYTES);
    geo_kernel<<<blocks, NTHR, SMEM_BYTES>>>(xyz, fm, bm, out, T);
}